// round 15
// baseline (speedup 1.0000x reference)
#include <cuda_runtime.h>
#include <cuda_fp16.h>
#include <math.h>

#define BB 128
#define TT 256
#define DD 512
#define LL 1024
#define NB 128   // persistent grid size (<=148 SMs -> co-resident)

// ---------- scratch (static device memory; no allocations) ----------
__device__ __align__(16) float g_xz[TT * BB * LL];   // x @ Wz_x^T + bz, [t][b][l]
__device__ __align__(16) float g_xr[TT * BB * LL];
__device__ __align__(16) float g_xi[TT * BB * LL];
__device__ __align__(16) __half g_hf [BB * LL];      // h  (single fp16)
__device__ __align__(16) float g_p1[8  * BB * 2048]; // K-split partials, phase 1
__device__ __align__(16) float g_p2[16 * BB * LL];   // K-split partials, phase 2
__device__ unsigned g_bar1 = 0;
__device__ unsigned g_bar2 = 0;

// ---- software grid barrier (persistent kernel) ----
__device__ __forceinline__ void grid_sync(unsigned target) {
    __syncthreads();
    if (threadIdx.x == 0) {
        __threadfence();
        atomicAdd(&g_bar1, 1u);
        unsigned v;
        do {
            asm volatile("ld.acquire.gpu.u32 %0, [%1];" : "=r"(v) : "l"(&g_bar1));
        } while (v < target);
    }
    __syncthreads();
}

// ---- FMA-pipe-only transcendentals (no MUFU, no branches) ----
__device__ __forceinline__ float exp_neg(float ax) {   // e^{-ax}, ax in [0, 43]
    float y = ax * -1.44269504f;
    float n = rintf(y);
    float f = y - n;
    float p = 0.00133336f;
    p = fmaf(p, f, 0.00961813f);
    p = fmaf(p, f, 0.05550411f);
    p = fmaf(p, f, 0.24022651f);
    p = fmaf(p, f, 0.69314718f);
    p = fmaf(p, f, 1.0f);
    return p * __int_as_float(((int)n + 127) << 23);
}
__device__ __forceinline__ float rcp_12(float d) {     // 1/d for d in (1,2]
    float r = fmaf(d, -0.47058824f, 1.41176471f);
    r = r * fmaf(-d, r, 2.0f);
    r = r * fmaf(-d, r, 2.0f);
    return r;
}
__device__ __forceinline__ float fast_sigmoid(float x) {
    float ax = fminf(fabsf(x), 30.f);
    float s = rcp_12(1.0f + exp_neg(ax));
    return (x >= 0.f) ? s : (1.0f - s);
}
__device__ __forceinline__ float fast_tanh(float x) {
    float ax = fminf(fabsf(x), 15.f);
    float t = exp_neg(2.0f * ax);
    float m = (1.0f - t) * rcp_12(1.0f + t);
    return (x >= 0.f) ? m : -m;
}

// ---- portable tensor-core primitives ----
__device__ __forceinline__ unsigned smem_u32(const void* p) {
    unsigned a;
    asm("{ .reg .u64 t; cvta.to.shared.u64 t, %1; cvt.u32.u64 %0, t; }" : "=r"(a) : "l"(p));
    return a;
}
__device__ __forceinline__ void ldsm4(unsigned (&r)[4], unsigned addr) {
    asm volatile("ldmatrix.sync.aligned.m8n8.x4.shared.b16 {%0,%1,%2,%3}, [%4];"
                 : "=r"(r[0]), "=r"(r[1]), "=r"(r[2]), "=r"(r[3]) : "r"(addr));
}
__device__ __forceinline__ void mma16816(float (&d)[4], const unsigned (&a)[4],
                                         unsigned b0, unsigned b1) {
    asm volatile("mma.sync.aligned.m16n8k16.row.col.f32.f16.f16.f32 "
                 "{%0,%1,%2,%3}, {%4,%5,%6,%7}, {%8,%9}, {%0,%1,%2,%3};"
                 : "+f"(d[0]), "+f"(d[1]), "+f"(d[2]), "+f"(d[3])
                 : "r"(a[0]), "r"(a[1]), "r"(a[2]), "r"(a[3]), "r"(b0), "r"(b1));
}

// ---- fp16 pack helpers ----
__device__ __forceinline__ unsigned pack_h2(float a, float b) {
    return (unsigned)__half_as_ushort(__float2half_rn(a)) |
           ((unsigned)__half_as_ushort(__float2half_rn(b)) << 16);
}
__device__ __forceinline__ float h2_lo(unsigned u) {
    return __half2float(__ushort_as_half((unsigned short)(u & 0xFFFF)));
}
__device__ __forceinline__ float h2_hi(unsigned u) {
    return __half2float(__ushort_as_half((unsigned short)(u >> 16)));
}

// ---- fp32 -> (fp16 hi, fp16 lo) split-stage into padded-row smem tile ----
template<int WIDTH, int SST>
__device__ __forceinline__ void stage_split(char* __restrict__ hiB, char* __restrict__ loB,
                                            const float* __restrict__ src, int srcStride, int c0)
{
    int tid = threadIdx.x;
    int r = tid >> 2, part = tid & 3;
    const int CH = WIDTH / 4;
    int kl0 = part * CH;
    const float* s = src + (size_t)r * srcStride + c0 + kl0;
    unsigned short* hp = (unsigned short*)hiB + r * SST + kl0;
    unsigned short* lp = (unsigned short*)loB + r * SST + kl0;
#pragma unroll
    for (int g = 0; g < CH / 8; g++) {
        float4 f0 = *(const float4*)(s + g * 8);
        float4 f1 = *(const float4*)(s + g * 8 + 4);
        float xs[8] = {f0.x, f0.y, f0.z, f0.w, f1.x, f1.y, f1.z, f1.w};
        unsigned hu[4], lu[4];
#pragma unroll
        for (int p = 0; p < 4; p++) {
            __half h0 = __float2half_rn(xs[2 * p]);
            __half h1 = __float2half_rn(xs[2 * p + 1]);
            float l0 = xs[2 * p]     - __half2float(h0);
            float l1 = xs[2 * p + 1] - __half2float(h1);
            hu[p] = (unsigned)__half_as_ushort(h0) | ((unsigned)__half_as_ushort(h1) << 16);
            lu[p] = pack_h2(l0, l1);
        }
        *(uint4*)(hp + g * 8) = make_uint4(hu[0], hu[1], hu[2], hu[3]);
        *(uint4*)(lp + g * 8) = make_uint4(lu[0], lu[1], lu[2], lu[3]);
    }
}

// ---- fp32 -> single fp16 stage ----
template<int WIDTH, int SST>
__device__ __forceinline__ void stage_single(char* __restrict__ dst,
                                             const float* __restrict__ src, int srcStride, int c0)
{
    int tid = threadIdx.x;
    int r = tid >> 2, part = tid & 3;
    const int CH = WIDTH / 4;
    int kl0 = part * CH;
    const float* s = src + (size_t)r * srcStride + c0 + kl0;
    unsigned short* dp = (unsigned short*)dst + r * SST + kl0;
#pragma unroll
    for (int g = 0; g < CH / 8; g++) {
        float4 f0 = *(const float4*)(s + g * 8);
        float4 f1 = *(const float4*)(s + g * 8 + 4);
        uint4 u;
        u.x = pack_h2(f0.x, f0.y);
        u.y = pack_h2(f0.z, f0.w);
        u.z = pack_h2(f1.x, f1.y);
        u.w = pack_h2(f1.z, f1.w);
        *(uint4*)(dp + g * 8) = u;
    }
}

// ---- pure-copy stage: fp16 gmem array -> padded smem ----
#define ASST 136
#define CSST 72
template<int WIDTH>
__device__ __forceinline__ void stage_copyA(char* __restrict__ dst,
                                            const __half* __restrict__ srcH, int c0)
{
    int tid = threadIdx.x;
    int r = tid >> 2, part = tid & 3;
    const int CH = WIDTH / 4;
    const uint4* sH = (const uint4*)(srcH + (size_t)r * LL + c0 + part * CH);
    uint4* dH = (uint4*)((unsigned short*)dst + r * ASST + part * CH);
#pragma unroll
    for (int i = 0; i < CH / 8; i++) dH[i] = sH[i];
}

// ---- warp-tile GEMM: CTA 128x128, 16 warps as 4(m)x4(n), warp tile 32x32 ----
template<int SSTA, int SSTB>
__device__ __forceinline__ void wgemm(unsigned aS, unsigned bHi, unsigned bLo,
                                      int ksteps, float (&acc)[2][4][4])
{
    int lane = threadIdx.x & 31, wid = threadIdx.x >> 5;
    int m0w = (wid & 3) * 32, n0w = (wid >> 2) * 32;
    unsigned aoff = ((m0w + (lane & 15)) * SSTA + ((lane >> 4) << 3)) * 2;
    unsigned boff = ((n0w + (lane & 7) + ((lane >> 4) & 1) * 8) * SSTB
                     + (((lane >> 3) & 1) << 3)) * 2;
    for (int ks = 0; ks < ksteps; ks++) {
        unsigned ka = aoff + ks * 32, kb = boff + ks * 32;
        unsigned bh[2][4], bl[2][4];
        ldsm4(bh[0], bHi + kb);
        ldsm4(bh[1], bHi + kb + 16 * SSTB * 2);
        ldsm4(bl[0], bLo + kb);
        ldsm4(bl[1], bLo + kb + 16 * SSTB * 2);
#pragma unroll
        for (int im = 0; im < 2; im++) {
            unsigned a[4];
            ldsm4(a, aS + ka + im * 16 * SSTA * 2);
#pragma unroll
            for (int ib = 0; ib < 2; ib++) {
                mma16816(acc[im][ib * 2 + 0], a, bh[ib][0], bh[ib][1]);
                mma16816(acc[im][ib * 2 + 1], a, bh[ib][2], bh[ib][3]);
                mma16816(acc[im][ib * 2 + 0], a, bl[ib][0], bl[ib][1]);
                mma16816(acc[im][ib * 2 + 1], a, bl[ib][2], bl[ib][3]);
            }
        }
    }
}

__device__ __forceinline__ void zero_acc(float (&acc)[2][4][4]) {
#pragma unroll
    for (int i = 0; i < 2; i++)
#pragma unroll
        for (int j = 0; j < 4; j++)
#pragma unroll
            for (int q = 0; q < 4; q++) acc[i][j][q] = 0.f;
}

__device__ __forceinline__ void store_acc(float* __restrict__ dst, int ldd,
                                          const float (&acc)[2][4][4])
{
    int lane = threadIdx.x & 31, wid = threadIdx.x >> 5;
    int m0w = (wid & 3) * 32, n0w = (wid >> 2) * 32;
    int r = lane >> 2, cp = (lane & 3) * 2;
#pragma unroll
    for (int im = 0; im < 2; im++)
#pragma unroll
        for (int in8 = 0; in8 < 4; in8++) {
            float* p = dst + (size_t)(m0w + im * 16 + r) * ldd + n0w + in8 * 8 + cp;
            *(float2*)p = make_float2(acc[im][in8][0], acc[im][in8][1]);
            *(float2*)(p + 8 * ldd) = make_float2(acc[im][in8][2], acc[im][in8][3]);
        }
}

// ================= xproj: x @ W_x^T + b (double-buffered K=128 chunks) =================
#define XSST 136
#define XTB  34816           // 128 x 136 halfs
#define XP_SMEM (6 * XTB)    // 2 x (AS, WH, WL)

__global__ void __launch_bounds__(512) xproj_kernel(
    const float* __restrict__ x,
    const float* __restrict__ Wz, const float* __restrict__ bz,
    const float* __restrict__ Wr, const float* __restrict__ br,
    const float* __restrict__ Wi, const float* __restrict__ bi)
{
    extern __shared__ char smb[];
    __shared__ float sbias[128];

    int tid = threadIdx.x;
    int g = blockIdx.x >> 3;
    int n0 = (blockIdx.x & 7) * 128;
    int m0 = blockIdx.y * 128;
    const float* W    = (g == 0) ? Wz : ((g == 1) ? Wr : Wi);
    const float* bias = (g == 0) ? bz : ((g == 1) ? br : bi);
    float* Xg         = (g == 0) ? g_xz : ((g == 1) ? g_xr : g_xi);

    if (tid < 128) sbias[tid] = bias[n0 + tid];

    char* AS[2] = { smb,           smb + 3 * XTB };
    char* WH[2] = { smb + XTB,     smb + 4 * XTB };
    char* WL[2] = { smb + 2 * XTB, smb + 5 * XTB };

    float acc[2][4][4];
    zero_acc(acc);

    // prologue: stage chunk 0
    stage_single<128, XSST>(AS[0], x + (size_t)m0 * DD, DD, 0);
    stage_split<128, XSST>(WH[0], WL[0], W + (size_t)n0 * 1536, 1536, 0);
    __syncthreads();

    for (int c = 0; c < 4; c++) {           // K=512 in 4 chunks of 128
        int cur = c & 1;
        wgemm<XSST, XSST>(smem_u32(AS[cur]), smem_u32(WH[cur]), smem_u32(WL[cur]), 8, acc);
        if (c < 3) {
            int nxt = cur ^ 1;
            int k0 = (c + 1) * 128;
            stage_single<128, XSST>(AS[nxt], x + (size_t)m0 * DD, DD, k0);
            stage_split<128, XSST>(WH[nxt], WL[nxt], W + (size_t)n0 * 1536, 1536, k0);
        }
        __syncthreads();
    }

    // epilogue: bias + scatter to [t][b][l]
    int lane = tid & 31, wid = tid >> 5;
    int m0w = (wid & 3) * 32, n0w = (wid >> 2) * 32;
    int r = lane >> 2, cp = (lane & 3) * 2;
#pragma unroll
    for (int im = 0; im < 2; im++) {
#pragma unroll
        for (int in8 = 0; in8 < 4; in8++) {
            int col = n0w + in8 * 8 + cp;
            float b0 = sbias[col], b1 = sbias[col + 1];
            int m = m0 + m0w + im * 16 + r;
            int t = m & 255, b = m >> 8;
            float* p = Xg + (size_t)t * (BB * LL) + (size_t)b * LL + n0 + col;
            *(float2*)p = make_float2(acc[im][in8][0] + b0, acc[im][in8][1] + b1);
            int m2 = m + 8;
            int t2 = m2 & 255, b2 = m2 >> 8;
            float* p2 = Xg + (size_t)t2 * (BB * LL) + (size_t)b2 * LL + n0 + col;
            *(float2*)p2 = make_float2(acc[im][in8][2] + b0, acc[im][in8][3] + b1);
        }
    }
}

// ================= persistent recurrence: 3 barriers/step =================
#define PR_AT    0
#define PR_WA_HI 34816
#define PR_WA_LO 69632
#define PR_WC_HI 104448
#define PR_WC_LO 122880
#define PR_SMEM  141312

__global__ void __launch_bounds__(512) gru_persistent(
    const float* __restrict__ Wz, const float* __restrict__ Wr,
    const float* __restrict__ Wi, float* __restrict__ out)
{
    extern __shared__ char smb[];
    int tid = threadIdx.x;
    int bx = blockIdx.x;
    unsigned target = 0;

    unsigned atS  = smem_u32(smb + PR_AT);
    unsigned waHi = smem_u32(smb + PR_WA_HI), waLo = smem_u32(smb + PR_WA_LO);
    unsigned wcHi = smem_u32(smb + PR_WC_HI), wcLo = smem_u32(smb + PR_WC_LO);

    // CTA roles
    int kidxA = bx >> 4;            // 0..7  (phase-A K-slice of 128)
    int n0A   = (bx & 15) * 128;    // over N=2048
    int kidxC = bx >> 3;            // 0..15 (phase-C K-slice of 64)
    int n0C   = (bx & 7) * 128;     // over N=1024

    // element slice for phase-D (float2 over [B][L])
    int e2 = bx * 512 + tid;
    int bE = e2 >> 9, l2 = e2 & 511;

    // rh-staging slice for phase C': row rC (=batch), 16 l-values
    int rC = tid >> 2, partC = tid & 3;
    int lC = kidxC * 64 + partC * 16;

    // one-time: weight slices -> smem fp16 hi/lo (reused for all 256 steps)
    {
        const float* wbA = (n0A < 1024) ? Wz + (size_t)n0A * 1536
                                        : Wr + (size_t)(n0A - 1024) * 1536;
        stage_split<128, ASST>(smb + PR_WA_HI, smb + PR_WA_LO, wbA, 1536, 512 + kidxA * 128);
        stage_split<64, CSST>(smb + PR_WC_HI, smb + PR_WC_LO,
                              Wi + (size_t)n0C * 1536, 1536, 512 + kidxC * 64);
    }
    // init h = 0
    ((unsigned*)g_hf)[e2] = 0u;
    target += NB; grid_sync(target);

    for (int t = 0; t < TT; ++t) {
        // ---- Phase A: h @ [Wzh | Wrh]^T partials (K-slice 128) ----
        {
            stage_copyA<128>(smb + PR_AT, g_hf, kidxA * 128);
            __syncthreads();
            float acc[2][4][4];
            zero_acc(acc);
            wgemm<ASST, ASST>(atS, waHi, waLo, 8, acc);
            store_acc(g_p1 + (size_t)kidxA * BB * 2048 + n0A, 2048, acc);
        }
        target += NB; grid_sync(target);

        // ---- Phase C': compute rh slice locally -> smem, then (r*h) @ Wih^T ----
        {
            // reduce r-partials for the 16 elements this thread stages
            float s[16];
#pragma unroll
            for (int q = 0; q < 4; q++) {
                float4 v = *(const float4*)(g_xr + (size_t)t * (BB * LL) + rC * LL + lC + q * 4);
                s[q * 4 + 0] = v.x; s[q * 4 + 1] = v.y;
                s[q * 4 + 2] = v.z; s[q * 4 + 3] = v.w;
            }
#pragma unroll
            for (int k = 0; k < 8; k++) {
                const float* pk = g_p1 + (size_t)k * BB * 2048 + rC * 2048 + 1024 + lC;
#pragma unroll
                for (int q = 0; q < 4; q++) {
                    float4 v = *(const float4*)(pk + q * 4);
                    s[q * 4 + 0] += v.x; s[q * 4 + 1] += v.y;
                    s[q * 4 + 2] += v.z; s[q * 4 + 3] += v.w;
                }
            }
            uint4 hv0 = *(const uint4*)(g_hf + (size_t)rC * LL + lC);
            uint4 hv1 = *(const uint4*)(g_hf + (size_t)rC * LL + lC + 8);
            unsigned hw[8] = {hv0.x, hv0.y, hv0.z, hv0.w, hv1.x, hv1.y, hv1.z, hv1.w};
            unsigned rh[8];
#pragma unroll
            for (int p = 0; p < 8; p++) {
                float r0 = fast_sigmoid(s[2 * p]);
                float r1 = fast_sigmoid(s[2 * p + 1]);
                rh[p] = pack_h2(r0 * h2_lo(hw[p]), r1 * h2_hi(hw[p]));
            }
            unsigned short* dp = (unsigned short*)(smb + PR_AT) + rC * ASST + partC * 16;
            *(uint4*)dp       = make_uint4(rh[0], rh[1], rh[2], rh[3]);
            *(uint4*)(dp + 8) = make_uint4(rh[4], rh[5], rh[6], rh[7]);
            __syncthreads();

            float acc[2][4][4];
            zero_acc(acc);
            wgemm<ASST, CSST>(atS, wcHi, wcLo, 4, acc);
            store_acc(g_p2 + (size_t)kidxC * BB * LL + n0C, 1024, acc);
        }
        target += NB; grid_sync(target);

        // ---- Phase D': z from p1+xz, c from p2+xi, h update, emit ----
        {
            float2 zs = ((const float2*)g_xz)[(size_t)t * 65536 + e2];
            const float2* P1 = (const float2*)g_p1;
#pragma unroll
            for (int k = 0; k < 8; k++) {
                float2 pz = P1[(size_t)k * 131072 + bE * 1024 + l2];
                zs.x += pz.x; zs.y += pz.y;
            }
            float2 c = ((const float2*)g_xi)[(size_t)t * 65536 + e2];
            const float2* P2 = (const float2*)g_p2;
#pragma unroll
            for (int k = 0; k < 16; k++) {
                float2 p = P2[(size_t)k * 65536 + e2];
                c.x += p.x; c.y += p.y;
            }
            unsigned hv = ((const unsigned*)g_hf)[e2];
            float h0 = h2_lo(hv), h1 = h2_hi(hv);
            float z0 = fast_sigmoid(zs.x);
            float z1 = fast_sigmoid(zs.y);
            float hn0 = (1.f - z0) * h0 + z0 * fast_tanh(c.x);
            float hn1 = (1.f - z1) * h1 + z1 * fast_tanh(c.y);
            ((float2*)out)[(size_t)t * 65536 + e2] = make_float2(hn0, hn1);
            ((unsigned*)g_hf)[e2] = pack_h2(hn0, hn1);
        }
        target += NB; grid_sync(target);
    }

    // exit protocol: last CTA resets barrier counters
    if (tid == 0) {
        __threadfence();
        unsigned done = atomicAdd(&g_bar2, 1u) + 1;
        if (done == NB) {
            g_bar1 = 0;
            g_bar2 = 0;
            __threadfence();
        }
    }
}

extern "C" void kernel_launch(void* const* d_in, const int* in_sizes, int n_in,
                              void* d_out, int out_size) {
    const float* x  = (const float*)d_in[0];
    const float* Wz = (const float*)d_in[1];
    const float* bz = (const float*)d_in[2];
    const float* Wr = (const float*)d_in[3];
    const float* br = (const float*)d_in[4];
    const float* Wi = (const float*)d_in[5];
    const float* bi = (const float*)d_in[6];
    float* out = (float*)d_out;

    cudaFuncSetAttribute(xproj_kernel, cudaFuncAttributeMaxDynamicSharedMemorySize, XP_SMEM);
    cudaFuncSetAttribute(gru_persistent, cudaFuncAttributeMaxDynamicSharedMemorySize, PR_SMEM);

    xproj_kernel<<<dim3(24, 256), 512, XP_SMEM>>>(x, Wz, bz, Wr, br, Wi, bi);
    gru_persistent<<<NB, 512, PR_SMEM>>>(Wz, Wr, Wi, out);
}

// round 16
// speedup vs baseline: 1.4197x; 1.4197x over previous
#include <cuda_runtime.h>
#include <cuda_fp16.h>
#include <math.h>

#define BB 128
#define TT 256
#define DD 512
#define LL 1024
#define NB 128   // persistent grid size (<=148 SMs -> co-resident)

// ---------- scratch (static device memory; no allocations) ----------
__device__ __align__(16) float g_xz[TT * BB * LL];   // x @ Wz_x^T + bz, [t][b][l]
__device__ __align__(16) float g_xr[TT * BB * LL];
__device__ __align__(16) float g_xi[TT * BB * LL];
__device__ __align__(16) __half g_hf [BB * LL];      // h  (single fp16)
__device__ __align__(16) __half g_rhf[BB * LL];      // r*h (single fp16)
__device__ __align__(16) float g_p1[8  * BB * 2048]; // K-split partials, phase 1
__device__ __align__(16) float g_p2[16 * BB * LL];   // K-split partials, phase 2
// precast inputs for xproj (one-time fp32 -> fp16)
__device__ __align__(16) __half g_xh [BB * TT * DD];       // x as fp16, rows m=b*T+t
__device__ __align__(16) __half g_wxh[3 * LL * DD];        // W x-part hi, [gate][n][k]
__device__ __align__(16) __half g_wxl[3 * LL * DD];        // W x-part lo
__device__ unsigned g_bar1 = 0;
__device__ unsigned g_bar2 = 0;

// ---- software grid barrier (persistent kernel) ----
__device__ __forceinline__ void grid_sync(unsigned target) {
    __syncthreads();
    if (threadIdx.x == 0) {
        __threadfence();
        atomicAdd(&g_bar1, 1u);
        unsigned v;
        do {
            asm volatile("ld.acquire.gpu.u32 %0, [%1];" : "=r"(v) : "l"(&g_bar1));
        } while (v < target);
    }
    __syncthreads();
}

// ---- FMA-pipe-only transcendentals (no MUFU, no branches) ----
__device__ __forceinline__ float exp_neg(float ax) {   // e^{-ax}, ax in [0, 43]
    float y = ax * -1.44269504f;
    float n = rintf(y);
    float f = y - n;
    float p = 0.00133336f;
    p = fmaf(p, f, 0.00961813f);
    p = fmaf(p, f, 0.05550411f);
    p = fmaf(p, f, 0.24022651f);
    p = fmaf(p, f, 0.69314718f);
    p = fmaf(p, f, 1.0f);
    return p * __int_as_float(((int)n + 127) << 23);
}
__device__ __forceinline__ float rcp_12(float d) {     // 1/d for d in (1,2]
    float r = fmaf(d, -0.47058824f, 1.41176471f);
    r = r * fmaf(-d, r, 2.0f);
    r = r * fmaf(-d, r, 2.0f);
    return r;
}
__device__ __forceinline__ float fast_sigmoid(float x) {
    float ax = fminf(fabsf(x), 30.f);
    float s = rcp_12(1.0f + exp_neg(ax));
    return (x >= 0.f) ? s : (1.0f - s);
}
__device__ __forceinline__ float fast_tanh(float x) {
    float ax = fminf(fabsf(x), 15.f);
    float t = exp_neg(2.0f * ax);
    float m = (1.0f - t) * rcp_12(1.0f + t);
    return (x >= 0.f) ? m : -m;
}

// ---- portable tensor-core primitives ----
__device__ __forceinline__ unsigned smem_u32(const void* p) {
    unsigned a;
    asm("{ .reg .u64 t; cvta.to.shared.u64 t, %1; cvt.u32.u64 %0, t; }" : "=r"(a) : "l"(p));
    return a;
}
__device__ __forceinline__ void ldsm4(unsigned (&r)[4], unsigned addr) {
    asm volatile("ldmatrix.sync.aligned.m8n8.x4.shared.b16 {%0,%1,%2,%3}, [%4];"
                 : "=r"(r[0]), "=r"(r[1]), "=r"(r[2]), "=r"(r[3]) : "r"(addr));
}
__device__ __forceinline__ void mma16816(float (&d)[4], const unsigned (&a)[4],
                                         unsigned b0, unsigned b1) {
    asm volatile("mma.sync.aligned.m16n8k16.row.col.f32.f16.f16.f32 "
                 "{%0,%1,%2,%3}, {%4,%5,%6,%7}, {%8,%9}, {%0,%1,%2,%3};"
                 : "+f"(d[0]), "+f"(d[1]), "+f"(d[2]), "+f"(d[3])
                 : "r"(a[0]), "r"(a[1]), "r"(a[2]), "r"(a[3]), "r"(b0), "r"(b1));
}

// ---- fp16 pack helpers ----
__device__ __forceinline__ unsigned pack_h2(float a, float b) {
    return (unsigned)__half_as_ushort(__float2half_rn(a)) |
           ((unsigned)__half_as_ushort(__float2half_rn(b)) << 16);
}
__device__ __forceinline__ float h2_lo(unsigned u) {
    return __half2float(__ushort_as_half((unsigned short)(u & 0xFFFF)));
}
__device__ __forceinline__ float h2_hi(unsigned u) {
    return __half2float(__ushort_as_half((unsigned short)(u >> 16)));
}

// ---- fp32 -> (fp16 hi, fp16 lo) split-stage into padded-row smem tile ----
template<int WIDTH, int SST>
__device__ __forceinline__ void stage_split(char* __restrict__ hiB, char* __restrict__ loB,
                                            const float* __restrict__ src, int srcStride, int c0)
{
    int tid = threadIdx.x;
    int r = tid >> 2, part = tid & 3;
    const int CH = WIDTH / 4;
    int kl0 = part * CH;
    const float* s = src + (size_t)r * srcStride + c0 + kl0;
    unsigned short* hp = (unsigned short*)hiB + r * SST + kl0;
    unsigned short* lp = (unsigned short*)loB + r * SST + kl0;
#pragma unroll
    for (int g = 0; g < CH / 8; g++) {
        float4 f0 = *(const float4*)(s + g * 8);
        float4 f1 = *(const float4*)(s + g * 8 + 4);
        float xs[8] = {f0.x, f0.y, f0.z, f0.w, f1.x, f1.y, f1.z, f1.w};
        unsigned hu[4], lu[4];
#pragma unroll
        for (int p = 0; p < 4; p++) {
            __half h0 = __float2half_rn(xs[2 * p]);
            __half h1 = __float2half_rn(xs[2 * p + 1]);
            float l0 = xs[2 * p]     - __half2float(h0);
            float l1 = xs[2 * p + 1] - __half2float(h1);
            hu[p] = (unsigned)__half_as_ushort(h0) | ((unsigned)__half_as_ushort(h1) << 16);
            lu[p] = pack_h2(l0, l1);
        }
        *(uint4*)(hp + g * 8) = make_uint4(hu[0], hu[1], hu[2], hu[3]);
        *(uint4*)(lp + g * 8) = make_uint4(lu[0], lu[1], lu[2], lu[3]);
    }
}

// ---- pure-copy stage: fp16 gmem (arbitrary row stride) -> padded smem ----
template<int WIDTH, int SST, int SRCSTRIDE>
__device__ __forceinline__ void stage_copy(char* __restrict__ dst,
                                           const __half* __restrict__ srcH, int c0)
{
    int tid = threadIdx.x;
    int r = tid >> 2, part = tid & 3;
    const int CH = WIDTH / 4;
    const uint4* sH = (const uint4*)(srcH + (size_t)r * SRCSTRIDE + c0 + part * CH);
    uint4* dH = (uint4*)((unsigned short*)dst + r * SST + part * CH);
#pragma unroll
    for (int i = 0; i < CH / 8; i++) dH[i] = sH[i];
}

#define ASST 136
#define CSST 72

// ---- warp-tile GEMM: CTA 128x128, 16 warps as 4(m)x4(n), warp tile 32x32 ----
template<int SSTA, int SSTB>
__device__ __forceinline__ void wgemm(unsigned aS, unsigned bHi, unsigned bLo,
                                      int ksteps, float (&acc)[2][4][4])
{
    int lane = threadIdx.x & 31, wid = threadIdx.x >> 5;
    int m0w = (wid & 3) * 32, n0w = (wid >> 2) * 32;
    unsigned aoff = ((m0w + (lane & 15)) * SSTA + ((lane >> 4) << 3)) * 2;
    unsigned boff = ((n0w + (lane & 7) + ((lane >> 4) & 1) * 8) * SSTB
                     + (((lane >> 3) & 1) << 3)) * 2;
    for (int ks = 0; ks < ksteps; ks++) {
        unsigned ka = aoff + ks * 32, kb = boff + ks * 32;
        unsigned bh[2][4], bl[2][4];
        ldsm4(bh[0], bHi + kb);
        ldsm4(bh[1], bHi + kb + 16 * SSTB * 2);
        ldsm4(bl[0], bLo + kb);
        ldsm4(bl[1], bLo + kb + 16 * SSTB * 2);
#pragma unroll
        for (int im = 0; im < 2; im++) {
            unsigned a[4];
            ldsm4(a, aS + ka + im * 16 * SSTA * 2);
#pragma unroll
            for (int ib = 0; ib < 2; ib++) {
                mma16816(acc[im][ib * 2 + 0], a, bh[ib][0], bh[ib][1]);
                mma16816(acc[im][ib * 2 + 1], a, bh[ib][2], bh[ib][3]);
                mma16816(acc[im][ib * 2 + 0], a, bl[ib][0], bl[ib][1]);
                mma16816(acc[im][ib * 2 + 1], a, bl[ib][2], bl[ib][3]);
            }
        }
    }
}

__device__ __forceinline__ void zero_acc(float (&acc)[2][4][4]) {
#pragma unroll
    for (int i = 0; i < 2; i++)
#pragma unroll
        for (int j = 0; j < 4; j++)
#pragma unroll
            for (int q = 0; q < 4; q++) acc[i][j][q] = 0.f;
}

__device__ __forceinline__ void store_acc(float* __restrict__ dst, int ldd,
                                          const float (&acc)[2][4][4])
{
    int lane = threadIdx.x & 31, wid = threadIdx.x >> 5;
    int m0w = (wid & 3) * 32, n0w = (wid >> 2) * 32;
    int r = lane >> 2, cp = (lane & 3) * 2;
#pragma unroll
    for (int im = 0; im < 2; im++)
#pragma unroll
        for (int in8 = 0; in8 < 4; in8++) {
            float* p = dst + (size_t)(m0w + im * 16 + r) * ldd + n0w + in8 * 8 + cp;
            *(float2*)p = make_float2(acc[im][in8][0], acc[im][in8][1]);
            *(float2*)(p + 8 * ldd) = make_float2(acc[im][in8][2], acc[im][in8][3]);
        }
}

// ================= precast: one-time fp32 -> fp16 of x and W x-parts =================
__global__ void __launch_bounds__(512) precast_x_kernel(const float* __restrict__ x) {
    int i = blockIdx.x * 512 + threadIdx.x;   // 2,097,152 threads, 8 floats each
    const float4* s = (const float4*)(x + (size_t)i * 8);
    float4 f0 = s[0], f1 = s[1];
    uint4 u;
    u.x = pack_h2(f0.x, f0.y);
    u.y = pack_h2(f0.z, f0.w);
    u.z = pack_h2(f1.x, f1.y);
    u.w = pack_h2(f1.z, f1.w);
    *(uint4*)(g_xh + (size_t)i * 8) = u;
}

__global__ void __launch_bounds__(512) precast_w_kernel(
    const float* __restrict__ Wz, const float* __restrict__ Wr,
    const float* __restrict__ Wi)
{
    int i = blockIdx.x * 512 + threadIdx.x;   // 196,608 threads, 8 floats each
    size_t i8 = (size_t)i * 8;
    int g = (int)(i8 >> 19);                  // / (1024*512)
    int rem = (int)(i8 & 0x7FFFF);
    int n = rem >> 9, k = rem & 511;
    const float* W = (g == 0) ? Wz : ((g == 1) ? Wr : Wi);
    const float* s = W + (size_t)n * 1536 + k;
    float4 f0 = *(const float4*)s, f1 = *(const float4*)(s + 4);
    float xs[8] = {f0.x, f0.y, f0.z, f0.w, f1.x, f1.y, f1.z, f1.w};
    unsigned hu[4], lu[4];
#pragma unroll
    for (int p = 0; p < 4; p++) {
        __half h0 = __float2half_rn(xs[2 * p]);
        __half h1 = __float2half_rn(xs[2 * p + 1]);
        float l0 = xs[2 * p]     - __half2float(h0);
        float l1 = xs[2 * p + 1] - __half2float(h1);
        hu[p] = (unsigned)__half_as_ushort(h0) | ((unsigned)__half_as_ushort(h1) << 16);
        lu[p] = pack_h2(l0, l1);
    }
    *(uint4*)(g_wxh + i8) = make_uint4(hu[0], hu[1], hu[2], hu[3]);
    *(uint4*)(g_wxl + i8) = make_uint4(lu[0], lu[1], lu[2], lu[3]);
}

// ================= xproj: x @ W_x^T + b, tensor cores (pure-copy staging) =============
#define XSST 72
#define XTB  18432
#define XP_SMEM (3 * XTB)

__global__ void __launch_bounds__(512) xproj_kernel(
    const float* __restrict__ bz, const float* __restrict__ br,
    const float* __restrict__ bi)
{
    extern __shared__ char smb[];
    __shared__ float sbias[128];
    char* AS = smb;
    char* WH = smb + XTB;
    char* WL = smb + 2 * XTB;

    int tid = threadIdx.x;
    int g = blockIdx.x >> 3;
    int n0 = (blockIdx.x & 7) * 128;
    int m0 = blockIdx.y * 128;
    const float* bias = (g == 0) ? bz : ((g == 1) ? br : bi);
    float* Xg         = (g == 0) ? g_xz : ((g == 1) ? g_xr : g_xi);
    const __half* xs  = g_xh + (size_t)m0 * DD;
    const __half* wh  = g_wxh + ((size_t)g * LL + n0) * DD;
    const __half* wl  = g_wxl + ((size_t)g * LL + n0) * DD;

    if (tid < 128) sbias[tid] = bias[n0 + tid];

    unsigned aS = smem_u32(AS), bHi = smem_u32(WH), bLo = smem_u32(WL);

    float acc[2][4][4];
    zero_acc(acc);

    for (int c = 0; c < 8; c++) {           // K=512 in 8 chunks of 64
        int k0 = c * 64;
        stage_copy<64, XSST, DD>(AS, xs, k0);
        stage_copy<64, XSST, DD>(WH, wh, k0);
        stage_copy<64, XSST, DD>(WL, wl, k0);
        __syncthreads();
        wgemm<XSST, XSST>(aS, bHi, bLo, 4, acc);
        __syncthreads();
    }

    // epilogue: bias + scatter to [t][b][l]
    int lane = tid & 31, wid = tid >> 5;
    int m0w = (wid & 3) * 32, n0w = (wid >> 2) * 32;
    int r = lane >> 2, cp = (lane & 3) * 2;
#pragma unroll
    for (int im = 0; im < 2; im++) {
#pragma unroll
        for (int in8 = 0; in8 < 4; in8++) {
            int col = n0w + in8 * 8 + cp;
            float b0 = sbias[col], b1 = sbias[col + 1];
            int m = m0 + m0w + im * 16 + r;
            int t = m & 255, b = m >> 8;
            float* p = Xg + (size_t)t * (BB * LL) + (size_t)b * LL + n0 + col;
            *(float2*)p = make_float2(acc[im][in8][0] + b0, acc[im][in8][1] + b1);
            int m2 = m + 8;
            int t2 = m2 & 255, b2 = m2 >> 8;
            float* p2 = Xg + (size_t)t2 * (BB * LL) + (size_t)b2 * LL + n0 + col;
            *(float2*)p2 = make_float2(acc[im][in8][2] + b0, acc[im][in8][3] + b1);
        }
    }
}

// ================= persistent recurrence (tensor cores, r14 layout) =================
#define PR_AT    0
#define PR_WA_HI 34816
#define PR_WA_LO 69632
#define PR_WC_HI 104448
#define PR_WC_LO 122880
#define PR_SMEM  141312

__global__ void __launch_bounds__(512) gru_persistent(
    const float* __restrict__ Wz, const float* __restrict__ Wr,
    const float* __restrict__ Wi, float* __restrict__ out)
{
    extern __shared__ char smb[];
    int tid = threadIdx.x;
    int bx = blockIdx.x;
    unsigned target = 0;

    unsigned atS  = smem_u32(smb + PR_AT);
    unsigned waHi = smem_u32(smb + PR_WA_HI), waLo = smem_u32(smb + PR_WA_LO);
    unsigned wcHi = smem_u32(smb + PR_WC_HI), wcLo = smem_u32(smb + PR_WC_LO);

    // CTA roles
    int kidxA = bx >> 4;            // 0..7  (phase-A K-slice of 128)
    int n0A   = (bx & 15) * 128;    // over N=2048
    int kidxC = bx >> 3;            // 0..15 (phase-C K-slice of 64)
    int n0C   = (bx & 7) * 128;     // over N=1024

    // element slice owned by this CTA for reduce phases (float2 over [B][L])
    int e2 = bx * 512 + tid;
    int bE = e2 >> 9, l2 = e2 & 511;

    // one-time: weight slices -> smem fp16 hi/lo (reused for all 256 steps)
    {
        const float* wbA = (n0A < 1024) ? Wz + (size_t)n0A * 1536
                                        : Wr + (size_t)(n0A - 1024) * 1536;
        stage_split<128, ASST>(smb + PR_WA_HI, smb + PR_WA_LO, wbA, 1536, 512 + kidxA * 128);
        stage_split<64, CSST>(smb + PR_WC_HI, smb + PR_WC_LO,
                              Wi + (size_t)n0C * 1536, 1536, 512 + kidxC * 64);
    }
    // init h = 0
    ((unsigned*)g_hf)[e2] = 0u;
    target += NB; grid_sync(target);

    for (int t = 0; t < TT; ++t) {
        float z0, z1, h0, h1;   // carried from phase B to phase D in registers

        // ---- Phase A: h @ [Wzh | Wrh]^T partials (K-slice 128) ----
        {
            stage_copy<128, ASST, LL>(smb + PR_AT, g_hf, kidxA * 128);
            __syncthreads();
            // prefetch phase-B inputs under the GEMM
            float2 pf_xz = ((const float2*)g_xz)[(size_t)t * 65536 + e2];
            float2 pf_xr = ((const float2*)g_xr)[(size_t)t * 65536 + e2];
            unsigned pf_h = ((const unsigned*)g_hf)[e2];

            float acc[2][4][4];
            zero_acc(acc);
            wgemm<ASST, ASST>(atS, waHi, waLo, 8, acc);
            store_acc(g_p1 + (size_t)kidxA * BB * 2048 + n0A, 2048, acc);

            h0 = h2_lo(pf_h);
            h1 = h2_hi(pf_h);
            target += NB; grid_sync(target);

            // ---- Phase B: reduce1 -> z (regs), rh (gmem fp16) ----
            const float2* P = (const float2*)g_p1;
            float2 zs = pf_xz;
            float2 rs = pf_xr;
#pragma unroll
            for (int k = 0; k < 8; k++) {
                float2 pz = P[(size_t)k * 131072 + bE * 1024 + l2];
                float2 pr = P[(size_t)k * 131072 + bE * 1024 + 512 + l2];
                zs.x += pz.x; zs.y += pz.y;
                rs.x += pr.x; rs.y += pr.y;
            }
            z0 = fast_sigmoid(zs.x);
            z1 = fast_sigmoid(zs.y);
            float r0 = fast_sigmoid(rs.x);
            float r1 = fast_sigmoid(rs.y);
            ((unsigned*)g_rhf)[e2] = pack_h2(r0 * h0, r1 * h1);
        }
        target += NB; grid_sync(target);

        // ---- Phase C: (r*h) @ Wih^T partials (K-slice 64) ----
        float2 pf_xi;
        {
            stage_copy<64, ASST, LL>(smb + PR_AT, g_rhf, kidxC * 64);
            __syncthreads();
            pf_xi = ((const float2*)g_xi)[(size_t)t * 65536 + e2];   // prefetch for D
            float acc[2][4][4];
            zero_acc(acc);
            wgemm<ASST, CSST>(atS, wcHi, wcLo, 4, acc);
            store_acc(g_p2 + (size_t)kidxC * BB * LL + n0C, 1024, acc);
        }
        target += NB; grid_sync(target);

        // ---- Phase D: reduce2 -> h_new, emit history ----
        {
            float2 c = pf_xi;
            const float2* P = (const float2*)g_p2;
#pragma unroll
            for (int k = 0; k < 16; k++) {
                float2 p = P[(size_t)k * 65536 + e2];
                c.x += p.x; c.y += p.y;
            }
            float hn0 = (1.f - z0) * h0 + z0 * fast_tanh(c.x);
            float hn1 = (1.f - z1) * h1 + z1 * fast_tanh(c.y);
            ((float2*)out)[(size_t)t * 65536 + e2] = make_float2(hn0, hn1);
            ((unsigned*)g_hf)[e2] = pack_h2(hn0, hn1);
        }
        target += NB; grid_sync(target);
    }

    // exit protocol: last CTA resets barrier counters
    if (tid == 0) {
        __threadfence();
        unsigned done = atomicAdd(&g_bar2, 1u) + 1;
        if (done == NB) {
            g_bar1 = 0;
            g_bar2 = 0;
            __threadfence();
        }
    }
}

extern "C" void kernel_launch(void* const* d_in, const int* in_sizes, int n_in,
                              void* d_out, int out_size) {
    const float* x  = (const float*)d_in[0];
    const float* Wz = (const float*)d_in[1];
    const float* bz = (const float*)d_in[2];
    const float* Wr = (const float*)d_in[3];
    const float* br = (const float*)d_in[4];
    const float* Wi = (const float*)d_in[5];
    const float* bi = (const float*)d_in[6];
    float* out = (float*)d_out;

    cudaFuncSetAttribute(xproj_kernel, cudaFuncAttributeMaxDynamicSharedMemorySize, XP_SMEM);
    cudaFuncSetAttribute(gru_persistent, cudaFuncAttributeMaxDynamicSharedMemorySize, PR_SMEM);

    precast_x_kernel<<<4096, 512>>>(x);          // 2,097,152 threads x 8 floats
    precast_w_kernel<<<384, 512>>>(Wz, Wr, Wi);  // 196,608 threads x 8 floats
    xproj_kernel<<<dim3(24, 256), 512, XP_SMEM>>>(bz, br, bi);
    gru_persistent<<<NB, 512, PR_SMEM>>>(Wz, Wr, Wi, out);
}

// round 17
// speedup vs baseline: 1.5572x; 1.0968x over previous
#include <cuda_runtime.h>
#include <cuda_fp16.h>
#include <math.h>

#define BB 128
#define TT 256
#define DD 512
#define LL 1024
#define NB 128   // persistent grid size (<=148 SMs -> co-resident)

// ---------- scratch (static device memory; no allocations) ----------
__device__ __align__(16) float g_xz[TT * BB * LL];   // x @ Wz_x^T + bz, [t][b][l]
__device__ __align__(16) float g_xr[TT * BB * LL];
__device__ __align__(16) float g_xi[TT * BB * LL];
__device__ __align__(16) __half g_hf [BB * LL];      // h  (single fp16)
__device__ __align__(16) __half g_rhf[BB * LL];      // r*h (single fp16)
__device__ __align__(16) float g_p1[8  * BB * 2048]; // K-split partials, phase 1
__device__ __align__(16) float g_p2[16 * BB * LL];   // K-split partials, phase 2
// precast inputs for xproj (one-time fp32 -> fp16)
__device__ __align__(16) __half g_xh [BB * TT * DD];       // x as fp16, rows m=b*T+t
__device__ __align__(16) __half g_wxh[3 * LL * DD];        // W x-part fp16, [gate][n][k]
__device__ unsigned g_bar1 = 0;
__device__ unsigned g_bar2 = 0;

// ---- software grid barrier (persistent kernel) ----
__device__ __forceinline__ void grid_sync(unsigned target) {
    __syncthreads();
    if (threadIdx.x == 0) {
        __threadfence();
        atomicAdd(&g_bar1, 1u);
        unsigned v;
        do {
            asm volatile("ld.acquire.gpu.u32 %0, [%1];" : "=r"(v) : "l"(&g_bar1));
        } while (v < target);
    }
    __syncthreads();
}

// ---- FMA-pipe-only transcendentals (no MUFU, no branches) ----
__device__ __forceinline__ float exp_neg(float ax) {   // e^{-ax}, ax in [0, 43]
    float y = ax * -1.44269504f;
    float n = rintf(y);
    float f = y - n;
    float p = 0.00133336f;
    p = fmaf(p, f, 0.00961813f);
    p = fmaf(p, f, 0.05550411f);
    p = fmaf(p, f, 0.24022651f);
    p = fmaf(p, f, 0.69314718f);
    p = fmaf(p, f, 1.0f);
    return p * __int_as_float(((int)n + 127) << 23);
}
__device__ __forceinline__ float rcp_12(float d) {     // 1/d for d in (1,2]
    float r = fmaf(d, -0.47058824f, 1.41176471f);
    r = r * fmaf(-d, r, 2.0f);
    r = r * fmaf(-d, r, 2.0f);
    return r;
}
__device__ __forceinline__ float fast_sigmoid(float x) {
    float ax = fminf(fabsf(x), 30.f);
    float s = rcp_12(1.0f + exp_neg(ax));
    return (x >= 0.f) ? s : (1.0f - s);
}
__device__ __forceinline__ float fast_tanh(float x) {
    float ax = fminf(fabsf(x), 15.f);
    float t = exp_neg(2.0f * ax);
    float m = (1.0f - t) * rcp_12(1.0f + t);
    return (x >= 0.f) ? m : -m;
}

// ---- portable tensor-core primitives ----
__device__ __forceinline__ unsigned smem_u32(const void* p) {
    unsigned a;
    asm("{ .reg .u64 t; cvta.to.shared.u64 t, %1; cvt.u32.u64 %0, t; }" : "=r"(a) : "l"(p));
    return a;
}
__device__ __forceinline__ void ldsm4(unsigned (&r)[4], unsigned addr) {
    asm volatile("ldmatrix.sync.aligned.m8n8.x4.shared.b16 {%0,%1,%2,%3}, [%4];"
                 : "=r"(r[0]), "=r"(r[1]), "=r"(r[2]), "=r"(r[3]) : "r"(addr));
}
__device__ __forceinline__ void mma16816(float (&d)[4], const unsigned (&a)[4],
                                         unsigned b0, unsigned b1) {
    asm volatile("mma.sync.aligned.m16n8k16.row.col.f32.f16.f16.f32 "
                 "{%0,%1,%2,%3}, {%4,%5,%6,%7}, {%8,%9}, {%0,%1,%2,%3};"
                 : "+f"(d[0]), "+f"(d[1]), "+f"(d[2]), "+f"(d[3])
                 : "r"(a[0]), "r"(a[1]), "r"(a[2]), "r"(a[3]), "r"(b0), "r"(b1));
}

// ---- fp16 pack helpers ----
__device__ __forceinline__ unsigned pack_h2(float a, float b) {
    return (unsigned)__half_as_ushort(__float2half_rn(a)) |
           ((unsigned)__half_as_ushort(__float2half_rn(b)) << 16);
}
__device__ __forceinline__ float h2_lo(unsigned u) {
    return __half2float(__ushort_as_half((unsigned short)(u & 0xFFFF)));
}
__device__ __forceinline__ float h2_hi(unsigned u) {
    return __half2float(__ushort_as_half((unsigned short)(u >> 16)));
}

// ---- fp32 -> single fp16 stage into padded-row smem tile ----
template<int WIDTH, int SST>
__device__ __forceinline__ void stage_single(char* __restrict__ dst,
                                             const float* __restrict__ src, int srcStride, int c0)
{
    int tid = threadIdx.x;
    int r = tid >> 2, part = tid & 3;
    const int CH = WIDTH / 4;
    int kl0 = part * CH;
    const float* s = src + (size_t)r * srcStride + c0 + kl0;
    unsigned short* dp = (unsigned short*)dst + r * SST + kl0;
#pragma unroll
    for (int g = 0; g < CH / 8; g++) {
        float4 f0 = *(const float4*)(s + g * 8);
        float4 f1 = *(const float4*)(s + g * 8 + 4);
        uint4 u;
        u.x = pack_h2(f0.x, f0.y);
        u.y = pack_h2(f0.z, f0.w);
        u.z = pack_h2(f1.x, f1.y);
        u.w = pack_h2(f1.z, f1.w);
        *(uint4*)(dp + g * 8) = u;
    }
}

// ---- pure-copy stage: fp16 gmem (arbitrary row stride) -> padded smem ----
template<int WIDTH, int SST, int SRCSTRIDE>
__device__ __forceinline__ void stage_copy(char* __restrict__ dst,
                                           const __half* __restrict__ srcH, int c0)
{
    int tid = threadIdx.x;
    int r = tid >> 2, part = tid & 3;
    const int CH = WIDTH / 4;
    const uint4* sH = (const uint4*)(srcH + (size_t)r * SRCSTRIDE + c0 + part * CH);
    uint4* dH = (uint4*)((unsigned short*)dst + r * SST + part * CH);
#pragma unroll
    for (int i = 0; i < CH / 8; i++) dH[i] = sH[i];
}

#define ASST 136
#define CSST 72

// ---- warp-tile GEMM: CTA 128x128, 16 warps as 4(m)x4(n), warp tile 32x32 ----
// Single-fp16 A and B: 8 MMAs, 4 ldsm per kstep per warp.
template<int SSTA, int SSTB>
__device__ __forceinline__ void wgemm1(unsigned aS, unsigned bS,
                                       int ksteps, float (&acc)[2][4][4])
{
    int lane = threadIdx.x & 31, wid = threadIdx.x >> 5;
    int m0w = (wid & 3) * 32, n0w = (wid >> 2) * 32;
    unsigned aoff = ((m0w + (lane & 15)) * SSTA + ((lane >> 4) << 3)) * 2;
    unsigned boff = ((n0w + (lane & 7) + ((lane >> 4) & 1) * 8) * SSTB
                     + (((lane >> 3) & 1) << 3)) * 2;
    for (int ks = 0; ks < ksteps; ks++) {
        unsigned ka = aoff + ks * 32, kb = boff + ks * 32;
        unsigned bh[2][4];
        ldsm4(bh[0], bS + kb);
        ldsm4(bh[1], bS + kb + 16 * SSTB * 2);
#pragma unroll
        for (int im = 0; im < 2; im++) {
            unsigned a[4];
            ldsm4(a, aS + ka + im * 16 * SSTA * 2);
#pragma unroll
            for (int ib = 0; ib < 2; ib++) {
                mma16816(acc[im][ib * 2 + 0], a, bh[ib][0], bh[ib][1]);
                mma16816(acc[im][ib * 2 + 1], a, bh[ib][2], bh[ib][3]);
            }
        }
    }
}

__device__ __forceinline__ void zero_acc(float (&acc)[2][4][4]) {
#pragma unroll
    for (int i = 0; i < 2; i++)
#pragma unroll
        for (int j = 0; j < 4; j++)
#pragma unroll
            for (int q = 0; q < 4; q++) acc[i][j][q] = 0.f;
}

__device__ __forceinline__ void store_acc(float* __restrict__ dst, int ldd,
                                          const float (&acc)[2][4][4])
{
    int lane = threadIdx.x & 31, wid = threadIdx.x >> 5;
    int m0w = (wid & 3) * 32, n0w = (wid >> 2) * 32;
    int r = lane >> 2, cp = (lane & 3) * 2;
#pragma unroll
    for (int im = 0; im < 2; im++)
#pragma unroll
        for (int in8 = 0; in8 < 4; in8++) {
            float* p = dst + (size_t)(m0w + im * 16 + r) * ldd + n0w + in8 * 8 + cp;
            *(float2*)p = make_float2(acc[im][in8][0], acc[im][in8][1]);
            *(float2*)(p + 8 * ldd) = make_float2(acc[im][in8][2], acc[im][in8][3]);
        }
}

// ================= precast: one-time fp32 -> fp16 of x and W x-parts =================
__global__ void __launch_bounds__(512) precast_x_kernel(const float* __restrict__ x) {
    int i = blockIdx.x * 512 + threadIdx.x;   // 2,097,152 threads, 8 floats each
    const float4* s = (const float4*)(x + (size_t)i * 8);
    float4 f0 = s[0], f1 = s[1];
    uint4 u;
    u.x = pack_h2(f0.x, f0.y);
    u.y = pack_h2(f0.z, f0.w);
    u.z = pack_h2(f1.x, f1.y);
    u.w = pack_h2(f1.z, f1.w);
    *(uint4*)(g_xh + (size_t)i * 8) = u;
}

__global__ void __launch_bounds__(512) precast_w_kernel(
    const float* __restrict__ Wz, const float* __restrict__ Wr,
    const float* __restrict__ Wi)
{
    int i = blockIdx.x * 512 + threadIdx.x;   // 196,608 threads, 8 floats each
    size_t i8 = (size_t)i * 8;
    int g = (int)(i8 >> 19);
    int rem = (int)(i8 & 0x7FFFF);
    int n = rem >> 9, k = rem & 511;
    const float* W = (g == 0) ? Wz : ((g == 1) ? Wr : Wi);
    const float* s = W + (size_t)n * 1536 + k;
    float4 f0 = *(const float4*)s, f1 = *(const float4*)(s + 4);
    uint4 u;
    u.x = pack_h2(f0.x, f0.y);
    u.y = pack_h2(f0.z, f0.w);
    u.z = pack_h2(f1.x, f1.y);
    u.w = pack_h2(f1.z, f1.w);
    *(uint4*)(g_wxh + i8) = u;
}

// ================= xproj: x @ W_x^T + b, tensor cores (pure-copy staging) =============
#define XSST 72
#define XTB  18432
#define XP_SMEM (2 * XTB)

__global__ void __launch_bounds__(512) xproj_kernel(
    const float* __restrict__ bz, const float* __restrict__ br,
    const float* __restrict__ bi)
{
    extern __shared__ char smb[];
    __shared__ float sbias[128];
    char* AS = smb;
    char* WH = smb + XTB;

    int tid = threadIdx.x;
    int g = blockIdx.x >> 3;
    int n0 = (blockIdx.x & 7) * 128;
    int m0 = blockIdx.y * 128;
    const float* bias = (g == 0) ? bz : ((g == 1) ? br : bi);
    float* Xg         = (g == 0) ? g_xz : ((g == 1) ? g_xr : g_xi);
    const __half* xs  = g_xh + (size_t)m0 * DD;
    const __half* wh  = g_wxh + ((size_t)g * LL + n0) * DD;

    if (tid < 128) sbias[tid] = bias[n0 + tid];

    unsigned aS = smem_u32(AS), bS = smem_u32(WH);

    float acc[2][4][4];
    zero_acc(acc);

    for (int c = 0; c < 8; c++) {           // K=512 in 8 chunks of 64
        int k0 = c * 64;
        stage_copy<64, XSST, DD>(AS, xs, k0);
        stage_copy<64, XSST, DD>(WH, wh, k0);
        __syncthreads();
        wgemm1<XSST, XSST>(aS, bS, 4, acc);
        __syncthreads();
    }

    // epilogue: bias + scatter to [t][b][l]
    int lane = tid & 31, wid = tid >> 5;
    int m0w = (wid & 3) * 32, n0w = (wid >> 2) * 32;
    int r = lane >> 2, cp = (lane & 3) * 2;
#pragma unroll
    for (int im = 0; im < 2; im++) {
#pragma unroll
        for (int in8 = 0; in8 < 4; in8++) {
            int col = n0w + in8 * 8 + cp;
            float b0 = sbias[col], b1 = sbias[col + 1];
            int m = m0 + m0w + im * 16 + r;
            int t = m & 255, b = m >> 8;
            float* p = Xg + (size_t)t * (BB * LL) + (size_t)b * LL + n0 + col;
            *(float2*)p = make_float2(acc[im][in8][0] + b0, acc[im][in8][1] + b1);
            int m2 = m + 8;
            int t2 = m2 & 255, b2 = m2 >> 8;
            float* p2 = Xg + (size_t)t2 * (BB * LL) + (size_t)b2 * LL + n0 + col;
            *(float2*)p2 = make_float2(acc[im][in8][2] + b0, acc[im][in8][3] + b1);
        }
    }
}

// ================= persistent recurrence (single-fp16 weights) =================
#define PR_AT  0
#define PR_WA  34816
#define PR_WC  69632
#define PR_SMEM 88064

__global__ void __launch_bounds__(512) gru_persistent(
    const float* __restrict__ Wz, const float* __restrict__ Wr,
    const float* __restrict__ Wi, float* __restrict__ out)
{
    extern __shared__ char smb[];
    int tid = threadIdx.x;
    int bx = blockIdx.x;
    unsigned target = 0;

    unsigned atS = smem_u32(smb + PR_AT);
    unsigned waS = smem_u32(smb + PR_WA);
    unsigned wcS = smem_u32(smb + PR_WC);

    // CTA roles
    int kidxA = bx >> 4;            // 0..7  (phase-A K-slice of 128)
    int n0A   = (bx & 15) * 128;    // over N=2048
    int kidxC = bx >> 3;            // 0..15 (phase-C K-slice of 64)
    int n0C   = (bx & 7) * 128;     // over N=1024

    // element slice owned by this CTA for reduce phases (float2 over [B][L])
    int e2 = bx * 512 + tid;
    int bE = e2 >> 9, l2 = e2 & 511;

    // one-time: weight slices -> smem fp16 (reused for all 256 steps)
    {
        const float* wbA = (n0A < 1024) ? Wz + (size_t)n0A * 1536
                                        : Wr + (size_t)(n0A - 1024) * 1536;
        stage_single<128, ASST>(smb + PR_WA, wbA, 1536, 512 + kidxA * 128);
        stage_single<64, CSST>(smb + PR_WC, Wi + (size_t)n0C * 1536, 1536, 512 + kidxC * 64);
    }
    // init h = 0
    ((unsigned*)g_hf)[e2] = 0u;
    target += NB; grid_sync(target);

    for (int t = 0; t < TT; ++t) {
        float z0, z1, h0, h1;   // carried from phase B to phase D in registers

        // ---- Phase A: h @ [Wzh | Wrh]^T partials (K-slice 128) ----
        {
            stage_copy<128, ASST, LL>(smb + PR_AT, g_hf, kidxA * 128);
            __syncthreads();
            // prefetch phase-B inputs under the GEMM
            float2 pf_xz = ((const float2*)g_xz)[(size_t)t * 65536 + e2];
            float2 pf_xr = ((const float2*)g_xr)[(size_t)t * 65536 + e2];
            unsigned pf_h = ((const unsigned*)g_hf)[e2];

            float acc[2][4][4];
            zero_acc(acc);
            wgemm1<ASST, ASST>(atS, waS, 8, acc);
            store_acc(g_p1 + (size_t)kidxA * BB * 2048 + n0A, 2048, acc);

            h0 = h2_lo(pf_h);
            h1 = h2_hi(pf_h);
            target += NB; grid_sync(target);

            // ---- Phase B: reduce1 -> z (regs), rh (gmem fp16) ----
            const float2* P = (const float2*)g_p1;
            float2 zs = pf_xz;
            float2 rs = pf_xr;
#pragma unroll
            for (int k = 0; k < 8; k++) {
                float2 pz = P[(size_t)k * 131072 + bE * 1024 + l2];
                float2 pr = P[(size_t)k * 131072 + bE * 1024 + 512 + l2];
                zs.x += pz.x; zs.y += pz.y;
                rs.x += pr.x; rs.y += pr.y;
            }
            z0 = fast_sigmoid(zs.x);
            z1 = fast_sigmoid(zs.y);
            float r0 = fast_sigmoid(rs.x);
            float r1 = fast_sigmoid(rs.y);
            ((unsigned*)g_rhf)[e2] = pack_h2(r0 * h0, r1 * h1);
        }
        target += NB; grid_sync(target);

        // ---- Phase C: (r*h) @ Wih^T partials (K-slice 64) ----
        float2 pf_xi;
        {
            stage_copy<64, ASST, LL>(smb + PR_AT, g_rhf, kidxC * 64);
            __syncthreads();
            pf_xi = ((const float2*)g_xi)[(size_t)t * 65536 + e2];   // prefetch for D
            float acc[2][4][4];
            zero_acc(acc);
            wgemm1<ASST, CSST>(atS, wcS, 4, acc);
            store_acc(g_p2 + (size_t)kidxC * BB * LL + n0C, 1024, acc);
        }
        target += NB; grid_sync(target);

        // ---- Phase D: reduce2 -> h_new, emit history ----
        {
            float2 c = pf_xi;
            const float2* P = (const float2*)g_p2;
#pragma unroll
            for (int k = 0; k < 16; k++) {
                float2 p = P[(size_t)k * 65536 + e2];
                c.x += p.x; c.y += p.y;
            }
            float hn0 = (1.f - z0) * h0 + z0 * fast_tanh(c.x);
            float hn1 = (1.f - z1) * h1 + z1 * fast_tanh(c.y);
            ((float2*)out)[(size_t)t * 65536 + e2] = make_float2(hn0, hn1);
            ((unsigned*)g_hf)[e2] = pack_h2(hn0, hn1);
        }
        target += NB; grid_sync(target);
    }

    // exit protocol: last CTA resets barrier counters
    if (tid == 0) {
        __threadfence();
        unsigned done = atomicAdd(&g_bar2, 1u) + 1;
        if (done == NB) {
            g_bar1 = 0;
            g_bar2 = 0;
            __threadfence();
        }
    }
}

extern "C" void kernel_launch(void* const* d_in, const int* in_sizes, int n_in,
                              void* d_out, int out_size) {
    const float* x  = (const float*)d_in[0];
    const float* Wz = (const float*)d_in[1];
    const float* bz = (const float*)d_in[2];
    const float* Wr = (const float*)d_in[3];
    const float* br = (const float*)d_in[4];
    const float* Wi = (const float*)d_in[5];
    const float* bi = (const float*)d_in[6];
    float* out = (float*)d_out;

    cudaFuncSetAttribute(xproj_kernel, cudaFuncAttributeMaxDynamicSharedMemorySize, XP_SMEM);
    cudaFuncSetAttribute(gru_persistent, cudaFuncAttributeMaxDynamicSharedMemorySize, PR_SMEM);

    precast_x_kernel<<<4096, 512>>>(x);
    precast_w_kernel<<<384, 512>>>(Wz, Wr, Wi);
    xproj_kernel<<<dim3(24, 256), 512, XP_SMEM>>>(bz, br, bi);
    gru_persistent<<<NB, 512, PR_SMEM>>>(Wz, Wr, Wi, out);
}